// round 5
// baseline (speedup 1.0000x reference)
#include <cuda_runtime.h>
#include <math.h>

#define NN   8192
#define DIN  256
#define DH   128
#define DO   64
#define CAP  1024

// ---------------- scratch ----------------
__device__ float g_Wh1[(size_t)NN * DH];   // 4 MB
__device__ float g_h1 [(size_t)NN * DH];   // 4 MB
__device__ float g_Wh2[(size_t)NN * DO];   // 2 MB
__device__ float g_f1a[NN], g_f2a[NN];
__device__ float g_f1b[NN], g_f2b[NN];
__device__ int   g_nbr[(size_t)NN * CAP];  // 32 MB neighbor lists (reused by layer 2)
__device__ int   g_cnt[NN];
__device__ float g_cs1[DH], g_cs2[DO];     // column sums (empty-row fallback)
__device__ int   g_key1, g_key2;           // monotone-encoded f2 maxima

// monotone int encoding of float for atomicMax (handles negatives)
__device__ __forceinline__ int   fenc(float f){ int k=__float_as_int(f); return k<0 ? (k^0x7FFFFFFF) : k; }
__device__ __forceinline__ float fdec(int k){ return __int_as_float(k<0 ? (k^0x7FFFFFFF) : k); }

// packed fp32x2 FMA (FFMA2) — 2x fp32 FMA throughput, exact fp32 rounding
__device__ __forceinline__ unsigned long long fma2(unsigned long long a, unsigned long long b, unsigned long long c){
    unsigned long long d;
    asm("fma.rn.f32x2 %0,%1,%2,%3;" : "=l"(d) : "l"(a), "l"(b), "l"(c));
    return d;
}
__device__ __forceinline__ unsigned long long dup2(float x){
    unsigned long long r; asm("mov.b64 %0,{%1,%1};" : "=l"(r) : "f"(x)); return r;
}

// ---------------- init ----------------
__global__ void k_init() {
    int t = threadIdx.x;
    if (t < DH) g_cs1[t] = 0.f;
    if (t < DO) g_cs2[t] = 0.f;
    if (t == 0) { g_key1 = 0x80000000; g_key2 = 0x80000000; }
}

// ---------------- layer1 projection: Wh1 = X @ W1 (8 rows/block, 2 cols/thread) ----------------
__global__ __launch_bounds__(64) void k_wh1(const float* __restrict__ X,
                                            const float* __restrict__ W1) {
    __shared__ float Xs[8][DIN];   // 8 KB
    int r0 = blockIdx.x * 8, tid = threadIdx.x;
    const float4* xp = (const float4*)(X + (size_t)r0 * DIN);
    float4* sp = (float4*)&Xs[0][0];
    for (int i = tid; i < 8 * DIN / 4; i += 64) sp[i] = xp[i];
    __syncthreads();
    float a0[8], a1r[8];
#pragma unroll
    for (int r = 0; r < 8; r++) { a0[r] = 0.f; a1r[r] = 0.f; }
#pragma unroll 2
    for (int t = 0; t < DIN; t++) {
        float w0 = W1[t * DH + tid];
        float w1 = W1[t * DH + tid + 64];
#pragma unroll
        for (int r = 0; r < 8; r++) {
            float x = Xs[r][t];
            a0[r]  = fmaf(x, w0, a0[r]);
            a1r[r] = fmaf(x, w1, a1r[r]);
        }
    }
#pragma unroll
    for (int r = 0; r < 8; r++) {
        g_Wh1[(size_t)(r0 + r) * DH + tid]      = a0[r];
        g_Wh1[(size_t)(r0 + r) * DH + tid + 64] = a1r[r];
    }
}

// ---------------- f1/f2 + global max (layer1): warp per row ----------------
__global__ __launch_bounds__(256) void k_feat1(const float* __restrict__ a1) {
    int w = threadIdx.x >> 5, l = threadIdx.x & 31;
    int row = blockIdx.x * 8 + w;
    float4 v = *(const float4*)&g_Wh1[(size_t)row * DH + l * 4];
    float4 p = *(const float4*)&a1[l * 4];
    float4 q = *(const float4*)&a1[DH + l * 4];
    float s1 = v.x * p.x + v.y * p.y + v.z * p.z + v.w * p.w;
    float s2 = v.x * q.x + v.y * q.y + v.z * q.z + v.w * q.w;
#pragma unroll
    for (int o = 16; o; o >>= 1) {
        s1 += __shfl_xor_sync(0xFFFFFFFFu, s1, o);
        s2 += __shfl_xor_sync(0xFFFFFFFFu, s2, o);
    }
    if (l == 0) { g_f1a[row] = s1; g_f2a[row] = s2; atomicMax(&g_key1, fenc(s2)); }
}

// ---------------- column sums (empty-row fallback) ----------------
__global__ void k_cs1() {
    int k = threadIdx.x; int r0 = blockIdx.x * 128;
    float s = 0.f;
    for (int r = r0; r < r0 + 128; r++) s += g_Wh1[(size_t)r * DH + k];
    atomicAdd(&g_cs1[k], s);
}
__global__ void k_cs2() {
    int k = threadIdx.x; int r0 = blockIdx.x * 128;
    float s = 0.f;
    for (int r = r0; r < r0 + 128; r++) s += g_Wh2[(size_t)r * DO + k];
    atomicAdd(&g_cs2[k], s);
}

// ---------------- layer1 fused: adj scan -> nbr list, att1 store, hp1, elu ----------------
__global__ __launch_bounds__(256) void k_att1(const float* __restrict__ adj,
                                              float* __restrict__ att) {
    __shared__ int   s_idx[CAP];
    __shared__ float s_p[CAP];
    __shared__ float s_red[256];
    __shared__ int   s_cnt;
    int row = blockIdx.x, tid = threadIdx.x;
    if (tid == 0) s_cnt = 0;
    __syncthreads();

    float f1 = g_f1a[row];
    float mm = f1 + fdec(g_key1);
    float c = mm > 0.f ? mm : 0.2f * mm;  // >= max_j e(i,j)

    const float4* arow = (const float4*)(adj + (size_t)row * NN);
    float4*       orow = (float4*)(att + (size_t)row * NN);
    for (int v = tid; v < NN / 4; v += 256) {
        float4 a = arow[v];
        orow[v] = make_float4(0.f, 0.f, 0.f, 0.f);
        if (a.x > 0.f) { int j = 4*v + 0; float e = f1 + g_f2a[j]; e = e > 0.f ? e : 0.2f * e;
                         int p = atomicAdd(&s_cnt, 1); if (p < CAP) { s_idx[p] = j; s_p[p] = __expf(e - c); } }
        if (a.y > 0.f) { int j = 4*v + 1; float e = f1 + g_f2a[j]; e = e > 0.f ? e : 0.2f * e;
                         int p = atomicAdd(&s_cnt, 1); if (p < CAP) { s_idx[p] = j; s_p[p] = __expf(e - c); } }
        if (a.z > 0.f) { int j = 4*v + 2; float e = f1 + g_f2a[j]; e = e > 0.f ? e : 0.2f * e;
                         int p = atomicAdd(&s_cnt, 1); if (p < CAP) { s_idx[p] = j; s_p[p] = __expf(e - c); } }
        if (a.w > 0.f) { int j = 4*v + 3; float e = f1 + g_f2a[j]; e = e > 0.f ? e : 0.2f * e;
                         int p = atomicAdd(&s_cnt, 1); if (p < CAP) { s_idx[p] = j; s_p[p] = __expf(e - c); } }
    }
    __syncthreads();
    int cnt = min(s_cnt, CAP);
    if (tid == 0) g_cnt[row] = cnt;

    float ps = 0.f;
    for (int t = tid; t < cnt; t += 256) ps += s_p[t];
    s_red[tid] = ps; __syncthreads();
    for (int s = 128; s > 0; s >>= 1) { if (tid < s) s_red[tid] += s_red[tid + s]; __syncthreads(); }
    float ssum = s_red[0];

    for (int t = tid; t < cnt; t += 256) g_nbr[(size_t)row * CAP + t] = s_idx[t];

    if (cnt == 0) {  // softmax of all -9e15 -> uniform 1/N
        for (int v = tid; v < NN; v += 256) att[(size_t)row * NN + v] = 1.0f / NN;
        if (tid < DH) {
            float hp = g_cs1[tid] * (1.0f / NN);
            g_h1[(size_t)row * DH + tid] = hp > 0.f ? hp : expm1f(hp);
        }
        return;
    }
    float inv = 1.f / ssum;
    for (int t = tid; t < cnt; t += 256)
        att[(size_t)row * NN + s_idx[t]] = s_p[t] * inv;

    int k = tid & 127, half = tid >> 7;
    float acc = 0.f;
    for (int t = half; t < cnt; t += 2)
        acc += s_p[t] * g_Wh1[(size_t)s_idx[t] * DH + k];
    __syncthreads();
    s_red[tid] = acc; __syncthreads();
    if (half == 0) {
        float hp = (s_red[k] + s_red[k + 128]) * inv;
        g_h1[(size_t)row * DH + k] = hp > 0.f ? hp : expm1f(hp);  // elu
    }
}

// ---------------- layer2 projection: Wh2 = h1 @ W2 (8 rows/block, 2 cols/thread) ----------------
__global__ __launch_bounds__(32) void k_wh2(const float* __restrict__ W2) {
    __shared__ float Xs[8][DH];   // 4 KB
    int r0 = blockIdx.x * 8, tid = threadIdx.x;
    const float4* xp = (const float4*)(g_h1 + (size_t)r0 * DH);
    float4* sp = (float4*)&Xs[0][0];
    for (int i = tid; i < 8 * DH / 4; i += 32) sp[i] = xp[i];
    __syncthreads();
    float a0[8], a1r[8];
#pragma unroll
    for (int r = 0; r < 8; r++) { a0[r] = 0.f; a1r[r] = 0.f; }
#pragma unroll 2
    for (int t = 0; t < DH; t++) {
        float w0 = W2[t * DO + tid];
        float w1 = W2[t * DO + tid + 32];
#pragma unroll
        for (int r = 0; r < 8; r++) {
            float x = Xs[r][t];
            a0[r]  = fmaf(x, w0, a0[r]);
            a1r[r] = fmaf(x, w1, a1r[r]);
        }
    }
#pragma unroll
    for (int r = 0; r < 8; r++) {
        g_Wh2[(size_t)(r0 + r) * DO + tid]      = a0[r];
        g_Wh2[(size_t)(r0 + r) * DO + tid + 32] = a1r[r];
    }
}

// ---------------- f1/f2 + global max (layer2): warp per row ----------------
__global__ __launch_bounds__(256) void k_feat2(const float* __restrict__ a2) {
    int w = threadIdx.x >> 5, l = threadIdx.x & 31;
    int row = blockIdx.x * 8 + w;
    float2 v = *(const float2*)&g_Wh2[(size_t)row * DO + l * 2];
    float2 p = *(const float2*)&a2[l * 2];
    float2 q = *(const float2*)&a2[DO + l * 2];
    float s1 = v.x * p.x + v.y * p.y;
    float s2 = v.x * q.x + v.y * q.y;
#pragma unroll
    for (int o = 16; o; o >>= 1) {
        s1 += __shfl_xor_sync(0xFFFFFFFFu, s1, o);
        s2 += __shfl_xor_sync(0xFFFFFFFFu, s2, o);
    }
    if (l == 0) { g_f1b[row] = s1; g_f2b[row] = s2; atomicMax(&g_key2, fenc(s2)); }
}

// ---------------- layer2 fused: reuse nbr list, softmax, h2 = att2 @ Wh2 ----------------
__global__ __launch_bounds__(128) void k_att2(float* __restrict__ h2) {
    __shared__ int   s_idx[CAP];
    __shared__ float s_p[CAP];
    __shared__ float s_red[128];
    int row = blockIdx.x, tid = threadIdx.x;
    int cnt = g_cnt[row];
    float f1 = g_f1b[row];
    float mm = f1 + fdec(g_key2);
    float c = mm > 0.f ? mm : 0.2f * mm;

    float ps = 0.f;
    for (int t = tid; t < cnt; t += 128) {
        int j = g_nbr[(size_t)row * CAP + t];
        float e = f1 + g_f2b[j]; e = e > 0.f ? e : 0.2f * e;
        float p = __expf(e - c);
        s_idx[t] = j; s_p[t] = p; ps += p;
    }
    s_red[tid] = ps; __syncthreads();
    for (int s = 64; s > 0; s >>= 1) { if (tid < s) s_red[tid] += s_red[tid + s]; __syncthreads(); }
    float ssum = s_red[0];

    if (cnt == 0) {
        if (tid < DO) h2[(size_t)row * DO + tid] = g_cs2[tid] * (1.0f / NN);
        return;
    }
    float inv = 1.f / ssum;
    int k = tid & 63, half = tid >> 6;
    float acc = 0.f;
    for (int t = half; t < cnt; t += 2)
        acc += s_p[t] * g_Wh2[(size_t)s_idx[t] * DO + k];
    __syncthreads();
    s_red[tid] = acc; __syncthreads();
    if (half == 0)
        h2[(size_t)row * DO + k] = (s_red[k] + s_red[k + 64]) * inv;
}

// ---------------- decoder: G = sigmoid(h2 @ h2^T) * row_mask  (FFMA2, 128x128 tile) ----------------
// smem: Asd[64][128] u64 (A values pre-duplicated) + Bs[64][128] f32 = 96 KB dynamic
__global__ __launch_bounds__(256, 2) void k_dec(const float* __restrict__ h2,
                                                float* __restrict__ G) {
    extern __shared__ unsigned char smraw[];
    unsigned long long* Asd = (unsigned long long*)smraw;          // [k][m] dup pairs
    float*              Bs  = (float*)(smraw + 64 * 128 * 8);      // [k][n]
    int tid = threadIdx.x;
    int tx = tid & 15, ty = tid >> 4;
    int M0 = blockIdx.y * 128, N0 = blockIdx.x * 128;

    {   // load + transpose + dup
        int r = tid >> 1, h = tid & 1;
        const float4* ap = (const float4*)(h2 + (size_t)(M0 + r) * DO) + h * 8;
        const float4* bp = (const float4*)(h2 + (size_t)(N0 + r) * DO) + h * 8;
#pragma unroll
        for (int j = 0; j < 8; j++) {
            float4 av = ap[j], bv = bp[j];
            int k = h * 32 + j * 4;
            Asd[(k + 0) * 128 + r] = dup2(av.x);
            Asd[(k + 1) * 128 + r] = dup2(av.y);
            Asd[(k + 2) * 128 + r] = dup2(av.z);
            Asd[(k + 3) * 128 + r] = dup2(av.w);
            Bs[(k + 0) * 128 + r] = bv.x;
            Bs[(k + 1) * 128 + r] = bv.y;
            Bs[(k + 2) * 128 + r] = bv.z;
            Bs[(k + 3) * 128 + r] = bv.w;
        }
    }
    __syncthreads();

    unsigned long long acc[8][4];
#pragma unroll
    for (int i = 0; i < 8; i++)
#pragma unroll
        for (int p = 0; p < 4; p++) acc[i][p] = 0ull;

#pragma unroll 2
    for (int k = 0; k < DO; k++) {
        const unsigned long long* ar = Asd + k * 128;
        const float*              br = Bs  + k * 128;
        ulonglong2 A0 = *(const ulonglong2*)(ar + ty * 4);
        ulonglong2 A1 = *(const ulonglong2*)(ar + ty * 4 + 2);
        ulonglong2 A2 = *(const ulonglong2*)(ar + 64 + ty * 4);
        ulonglong2 A3 = *(const ulonglong2*)(ar + 64 + ty * 4 + 2);
        ulonglong2 B0 = *(const ulonglong2*)(br + tx * 4);        // pairs (n,n+1)
        ulonglong2 B1 = *(const ulonglong2*)(br + 64 + tx * 4);
        unsigned long long a[8] = {A0.x, A0.y, A1.x, A1.y, A2.x, A2.y, A3.x, A3.y};
        unsigned long long b[4] = {B0.x, B0.y, B1.x, B1.y};
#pragma unroll
        for (int i = 0; i < 8; i++)
#pragma unroll
            for (int p = 0; p < 4; p++)
                acc[i][p] = fma2(a[i], b[p], acc[i][p]);
    }

#pragma unroll
    for (int i = 0; i < 8; i++) {
        int m = M0 + (i < 4 ? ty * 4 + i : 64 + ty * 4 + (i - 4));
        float mask = g_cnt[m] > 0 ? 1.f : 0.f;
        float v[8];
#pragma unroll
        for (int p = 0; p < 4; p++) {
            v[p * 2 + 0] = __uint_as_float((unsigned)acc[i][p]);
            v[p * 2 + 1] = __uint_as_float((unsigned)(acc[i][p] >> 32));
        }
        float4 o0, o1;
        o0.x = mask / (1.f + __expf(-v[0])); o0.y = mask / (1.f + __expf(-v[1]));
        o0.z = mask / (1.f + __expf(-v[2])); o0.w = mask / (1.f + __expf(-v[3]));
        o1.x = mask / (1.f + __expf(-v[4])); o1.y = mask / (1.f + __expf(-v[5]));
        o1.z = mask / (1.f + __expf(-v[6])); o1.w = mask / (1.f + __expf(-v[7]));
        *(float4*)&G[(size_t)m * NN + N0 + tx * 4]      = o0;
        *(float4*)&G[(size_t)m * NN + N0 + 64 + tx * 4] = o1;
    }
}

// ---------------- launch ----------------
extern "C" void kernel_launch(void* const* d_in, const int* in_sizes, int n_in,
                              void* d_out, int out_size) {
    const float* X   = (const float*)d_in[0];
    const float* adj = (const float*)d_in[1];
    const float* W1  = (const float*)d_in[2];
    const float* a1  = (const float*)d_in[3];
    const float* W2  = (const float*)d_in[4];
    const float* a2  = (const float*)d_in[5];

    float* out = (float*)d_out;
    float* h2  = out;                                  // [NN, DO]
    float* gen = out + (size_t)NN * DO;                // [NN, NN]
    float* att = gen + (size_t)NN * NN;                // [NN, NN]

    k_init<<<1, 128>>>();
    k_wh1<<<NN / 8, 64>>>(X, W1);
    k_cs1<<<64, 128>>>();
    k_feat1<<<NN / 8, 256>>>(a1);
    k_att1<<<NN, 256>>>(adj, att);
    k_wh2<<<NN / 8, 32>>>(W2);
    k_cs2<<<64, 64>>>();
    k_feat2<<<NN / 8, 256>>>(a2);
    k_att2<<<NN, 128>>>(h2);

    static int smem_set = 0;
    if (!smem_set) {
        cudaFuncSetAttribute(k_dec, cudaFuncAttributeMaxDynamicSharedMemorySize, 96 * 1024);
        smem_set = 1;
    }
    dim3 gdim(NN / 128, NN / 128), bdim(256);
    k_dec<<<gdim, bdim, 96 * 1024>>>(h2, gen);
}